// round 2
// baseline (speedup 1.0000x reference)
#include <cuda_runtime.h>
#include <math.h>

#define NC 100000
#define NM 50000
#define NE 1000000

// ---------------- scratch (__device__ globals: allocation-free) ----------------
__device__ float g_mean_m[NM * 128];
__device__ float g_mean_c[NC * 128];
__device__ float g_hm[NM * 128];
__device__ float g_hc[NC * 128];
__device__ int   g_cnt_m[NM], g_cnt_c[NC];
__device__ int   g_off_m[NM + 1], g_off_c[NC + 1];
__device__ int   g_cur_m[NM], g_cur_c[NC];
__device__ int   g_csr_cm[NE];   // src card ids grouped by merchant dst
__device__ int   g_csr_mc[NE];   // src merchant ids grouped by card dst

// ---------------- packed f32x2 helpers (Blackwell) ----------------
__device__ __forceinline__ unsigned long long pack2(float x) {
    unsigned long long r;
    asm("mov.b64 %0, {%1, %1};" : "=l"(r) : "f"(x));
    return r;
}
__device__ __forceinline__ void ffma2(unsigned long long& d, unsigned long long a,
                                      unsigned long long b) {
    asm("fma.rn.f32x2 %0, %1, %2, %0;" : "+l"(d) : "l"(a), "l"(b));
}
__device__ __forceinline__ float2 unpack2(unsigned long long v) {
    float2 f;
    asm("mov.b64 {%0, %1}, %2;" : "=f"(f.x), "=f"(f.y) : "l"(v));
    return f;
}

// ---------------- CSR build ----------------
__global__ void k_zero() {
    int i = blockIdx.x * blockDim.x + threadIdx.x;
    if (i < NC) { g_cnt_c[i] = 0; g_cur_c[i] = 0; }
    if (i < NM) { g_cnt_m[i] = 0; g_cur_m[i] = 0; }
}

__global__ void k_count(const int* __restrict__ dcm, const int* __restrict__ dmc) {
    for (int i = blockIdx.x * blockDim.x + threadIdx.x; i < NE;
         i += gridDim.x * blockDim.x) {
        atomicAdd(&g_cnt_m[dcm[i]], 1);
        atomicAdd(&g_cnt_c[dmc[i]], 1);
    }
}

// single-block exclusive scan; WHICH: 0 = merchants (NM), 1 = cards (NC)
template <int WHICH>
__global__ void k_scan() {
    const int N = WHICH ? NC : NM;
    const int* __restrict__ cnt = WHICH ? g_cnt_c : g_cnt_m;
    int* __restrict__ off = WHICH ? g_off_c : g_off_m;
    __shared__ int sh[1024];
    int t = threadIdx.x;
    const int per = (N + 1023) >> 10;
    int start = t * per;
    int end = min(start + per, N);
    int s = 0;
    for (int i = start; i < end; i++) s += cnt[i];
    sh[t] = s;
    __syncthreads();
    for (int d = 1; d < 1024; d <<= 1) {
        int v = (t >= d) ? sh[t - d] : 0;
        __syncthreads();
        sh[t] += v;
        __syncthreads();
    }
    int run = (t ? sh[t - 1] : 0);
    for (int i = start; i < end; i++) { off[i] = run; run += cnt[i]; }
    if (end == N) off[N] = run;
}

__global__ void k_fill(const int* __restrict__ scm, const int* __restrict__ dcm,
                       const int* __restrict__ smc, const int* __restrict__ dmc) {
    for (int i = blockIdx.x * blockDim.x + threadIdx.x; i < NE;
         i += gridDim.x * blockDim.x) {
        int d = dcm[i];
        int p = g_off_m[d] + atomicAdd(&g_cur_m[d], 1);
        g_csr_cm[p] = scm[i];
        int d2 = dmc[i];
        int p2 = g_off_c[d2] + atomicAdd(&g_cur_c[d2], 1);
        g_csr_mc[p2] = smc[i];
    }
}

// ---------------- gather-style mean aggregation (no float atomics) ----------------
// GRAPH: 0 = cm edges (dst = merchants), 1 = mc edges (dst = cards)
// KVEC:  floats per lane (2 -> K=64, 4 -> K=128)
// XS:    0 -> xext argument, 1 -> g_hm, 2 -> g_hc
template <int GRAPH, int KVEC, int XS>
__global__ void k_aggregate(const float* __restrict__ xext) {
    const int* __restrict__ off = GRAPH ? g_off_c : g_off_m;
    const int* __restrict__ cnt = GRAPH ? g_cnt_c : g_cnt_m;
    const int* __restrict__ csr = GRAPH ? g_csr_mc : g_csr_cm;
    float* __restrict__ mean = GRAPH ? g_mean_c : g_mean_m;
    const int nn = GRAPH ? NC : NM;
    const float* __restrict__ xsrc = (XS == 0) ? xext : (XS == 1 ? g_hm : g_hc);

    int w = (blockIdx.x * blockDim.x + threadIdx.x) >> 5;
    if (w >= nn) return;
    int lane = threadIdx.x & 31;
    int b = off[w], e = off[w + 1];

    if (KVEC == 2) {
        float ax = 0.f, ay = 0.f;
        for (int j = b; j < e; j++) {
            int s = csr[j];
            float2 v = ((const float2*)(xsrc + (size_t)s * 64))[lane];
            ax += v.x; ay += v.y;
        }
        float r = 1.f / fmaxf((float)cnt[w], 1.f);
        ((float2*)(mean + (size_t)w * 64))[lane] = make_float2(ax * r, ay * r);
    } else {
        float ax = 0.f, ay = 0.f, az = 0.f, aw = 0.f;
        for (int j = b; j < e; j++) {
            int s = csr[j];
            float4 v = ((const float4*)(xsrc + (size_t)s * 128))[lane];
            ax += v.x; ay += v.y; az += v.z; aw += v.w;
        }
        float r = 1.f / fmaxf((float)cnt[w], 1.f);
        float4 o;
        o.x = ax * r; o.y = ay * r; o.z = az * r; o.w = aw * r;
        ((float4*)(mean + (size_t)w * 128))[lane] = o;
    }
}

// ---------------- fused SAGE GEMM: out = relu([mean|xdst] @ [Wl;Wr] + b) ------------
// 32 rows x 128 cols per block, 256 threads, 4x4 micro-tile, fma.rn.f32x2 inner loop.
// MSEL: 0 -> g_mean_m, 1 -> g_mean_c
// XSEL: 0 -> xext, 1 -> g_hm, 2 -> g_hc
// OSEL: 0 -> oext, 1 -> g_hm, 2 -> g_hc
template <int MSEL, int XSEL, int OSEL>
__global__ __launch_bounds__(256) void k_gemm(const float* __restrict__ xext,
                                              float* __restrict__ oext,
                                              const float* __restrict__ Wl,
                                              const float* __restrict__ Wr,
                                              const float* __restrict__ bias,
                                              int nrows, int KH) {
    const float* __restrict__ mean = MSEL ? g_mean_c : g_mean_m;
    const float* __restrict__ xdst = (XSEL == 0) ? xext : (XSEL == 1 ? g_hm : g_hc);
    float* __restrict__ out = (OSEL == 0) ? oext : (OSEL == 1 ? g_hm : g_hc);

    __shared__ float Ws[64][128];
    __shared__ float As[64][33];

    int t = threadIdx.x;
    int c0 = (t & 31) * 4;
    int r0 = (t >> 5) * 4;
    int row0 = blockIdx.x * 32;

    unsigned long long acc[4][2];
#pragma unroll
    for (int r = 0; r < 4; r++) { acc[r][0] = 0ull; acc[r][1] = 0ull; }

    int nch = (2 * KH) >> 6;
    for (int ch = 0; ch < nch; ++ch) {
        int kbase = ch * 64;
        const float* Asrc;
        const float* Wsrc;
        int kloc;
        if (kbase < KH) {
            Asrc = mean; kloc = kbase; Wsrc = Wl + (size_t)kbase * 128;
        } else {
            Asrc = xdst; kloc = kbase - KH; Wsrc = Wr + (size_t)(kbase - KH) * 128;
        }
        __syncthreads();
#pragma unroll
        for (int i = 0; i < 8; i++) {  // 2048 float4 -> Ws
            int lin = t + i * 256;
            int k = lin >> 5, c4 = lin & 31;
            *(float4*)&Ws[k][c4 * 4] = *(const float4*)(Wsrc + (size_t)k * 128 + c4 * 4);
        }
#pragma unroll
        for (int i = 0; i < 8; i++) {  // 2048 floats -> As (transposed)
            int lin = t + i * 256;
            int k = lin & 63, r = lin >> 6;
            int row = row0 + r;
            if (row >= nrows) row = nrows - 1;
            As[k][r] = Asrc[(size_t)row * KH + kloc + k];
        }
        __syncthreads();
#pragma unroll 8
        for (int k = 0; k < 64; k++) {
            ulonglong2 w = *(const ulonglong2*)&Ws[k][c0];
#pragma unroll
            for (int r = 0; r < 4; r++) {
                unsigned long long aa = pack2(As[k][r0 + r]);
                ffma2(acc[r][0], aa, w.x);
                ffma2(acc[r][1], aa, w.y);
            }
        }
    }

    float4 b4 = *(const float4*)(bias + c0);
#pragma unroll
    for (int r = 0; r < 4; r++) {
        int row = row0 + r0 + r;
        if (row >= nrows) continue;
        float2 lo = unpack2(acc[r][0]);
        float2 hi = unpack2(acc[r][1]);
        float4 v;
        v.x = fmaxf(lo.x + b4.x, 0.f);
        v.y = fmaxf(lo.y + b4.y, 0.f);
        v.z = fmaxf(hi.x + b4.z, 0.f);
        v.w = fmaxf(hi.y + b4.w, 0.f);
        *(float4*)(out + (size_t)row * 128 + c0) = v;
    }
}

// ---------------- fused heads: class MLP + shared risk scorer ----------------
// phase A: T = relu(h @ [cW1|rW1] + [cb1|rb1])  (32 rows x 128 cols, same micro-kernel)
// phase B: pred = T[:, :64] @ cW2 + cb2 ; risk = sigmoid(T[:, 64:] @ rW2 + rb2)
__global__ __launch_bounds__(256) void k_head(const float* __restrict__ h, int nrows,
                                              const float* __restrict__ cW1,
                                              const float* __restrict__ cb1,
                                              const float* __restrict__ cW2,
                                              const float* __restrict__ cb2,
                                              const float* __restrict__ rW1,
                                              const float* __restrict__ rb1,
                                              const float* __restrict__ rW2,
                                              const float* __restrict__ rb2,
                                              float* __restrict__ pred,
                                              float* __restrict__ risk) {
    __shared__ float Ws[64][128];
    __shared__ float As[64][33];
    __shared__ float Ts[32][132];

    int t = threadIdx.x;
    int c0 = (t & 31) * 4;
    int r0 = (t >> 5) * 4;
    int row0 = blockIdx.x * 32;

    unsigned long long acc[4][2];
#pragma unroll
    for (int r = 0; r < 4; r++) { acc[r][0] = 0ull; acc[r][1] = 0ull; }

    for (int ch = 0; ch < 2; ++ch) {
        int kbase = ch * 64;
        __syncthreads();
#pragma unroll
        for (int i = 0; i < 8; i++) {
            int lin = t + i * 256;
            int k = lin >> 5, c4 = lin & 31;
            const float* src = (c4 < 16) ? (cW1 + (size_t)(kbase + k) * 64 + c4 * 4)
                                         : (rW1 + (size_t)(kbase + k) * 64 + (c4 - 16) * 4);
            *(float4*)&Ws[k][c4 * 4] = *(const float4*)src;
        }
#pragma unroll
        for (int i = 0; i < 8; i++) {
            int lin = t + i * 256;
            int k = lin & 63, r = lin >> 6;
            int row = row0 + r;
            if (row >= nrows) row = nrows - 1;
            As[k][r] = h[(size_t)row * 128 + kbase + k];
        }
        __syncthreads();
#pragma unroll 8
        for (int k = 0; k < 64; k++) {
            ulonglong2 w = *(const ulonglong2*)&Ws[k][c0];
#pragma unroll
            for (int r = 0; r < 4; r++) {
                unsigned long long aa = pack2(As[k][r0 + r]);
                ffma2(acc[r][0], aa, w.x);
                ffma2(acc[r][1], aa, w.y);
            }
        }
    }

    float4 b4 = (c0 < 64) ? *(const float4*)(cb1 + c0) : *(const float4*)(rb1 + c0 - 64);
#pragma unroll
    for (int r = 0; r < 4; r++) {
        float2 lo = unpack2(acc[r][0]);
        float2 hi = unpack2(acc[r][1]);
        float4 v;
        v.x = fmaxf(lo.x + b4.x, 0.f);
        v.y = fmaxf(lo.y + b4.y, 0.f);
        v.z = fmaxf(hi.x + b4.z, 0.f);
        v.w = fmaxf(hi.y + b4.w, 0.f);
        *(float4*)&Ts[r0 + r][c0] = v;
    }
    __syncthreads();

    int wid = t >> 5, lane = t & 31;
    float w00 = cW2[lane * 2], w01 = cW2[lane * 2 + 1];
    float w10 = cW2[(lane + 32) * 2], w11 = cW2[(lane + 32) * 2 + 1];
    float rw0 = rW2[lane], rw1 = rW2[lane + 32];
    for (int rr = wid; rr < 32; rr += 8) {
        int row = row0 + rr;
        float t1a = Ts[rr][lane], t1b = Ts[rr][lane + 32];
        float t2a = Ts[rr][64 + lane], t2b = Ts[rr][96 + lane];
        float p0 = t1a * w00 + t1b * w10;
        float p1 = t1a * w01 + t1b * w11;
        float rk = t2a * rw0 + t2b * rw1;
#pragma unroll
        for (int d = 16; d; d >>= 1) {
            p0 += __shfl_xor_sync(0xffffffffu, p0, d);
            p1 += __shfl_xor_sync(0xffffffffu, p1, d);
            rk += __shfl_xor_sync(0xffffffffu, rk, d);
        }
        if (lane == 0 && row < nrows) {
            pred[(size_t)row * 2 + 0] = p0 + cb2[0];
            pred[(size_t)row * 2 + 1] = p1 + cb2[1];
            float x = rk + rb2[0];
            risk[row] = 1.f / (1.f + __expf(-x));
        }
    }
}

// ---------------- launcher ----------------
extern "C" void kernel_launch(void* const* d_in, const int* in_sizes, int n_in,
                              void* d_out, int out_size) {
    const float* x_card  = (const float*)d_in[0];
    const float* x_merch = (const float*)d_in[1];
    const int* src_cm = (const int*)d_in[2];
    const int* dst_cm = (const int*)d_in[3];
    const int* src_mc = (const int*)d_in[4];
    const int* dst_mc = (const int*)d_in[5];
    const float* Wl0_cm = (const float*)d_in[6];
    const float* bl0_cm = (const float*)d_in[7];
    const float* Wr0_cm = (const float*)d_in[8];
    const float* Wl0_mc = (const float*)d_in[9];
    const float* bl0_mc = (const float*)d_in[10];
    const float* Wr0_mc = (const float*)d_in[11];
    const float* Wl1_cm = (const float*)d_in[12];
    const float* bl1_cm = (const float*)d_in[13];
    const float* Wr1_cm = (const float*)d_in[14];
    const float* Wl1_mc = (const float*)d_in[15];
    const float* bl1_mc = (const float*)d_in[16];
    const float* Wr1_mc = (const float*)d_in[17];
    const float* cW1c = (const float*)d_in[18];
    const float* cb1c = (const float*)d_in[19];
    const float* cW2c = (const float*)d_in[20];
    const float* cb2c = (const float*)d_in[21];
    const float* cW1m = (const float*)d_in[22];
    const float* cb1m = (const float*)d_in[23];
    const float* cW2m = (const float*)d_in[24];
    const float* cb2m = (const float*)d_in[25];
    const float* rW1 = (const float*)d_in[26];
    const float* rb1 = (const float*)d_in[27];
    const float* rW2 = (const float*)d_in[28];
    const float* rb2 = (const float*)d_in[29];

    float* out = (float*)d_out;
    float* o_hc2 = out;                       // [NC,128]
    float* o_hm2 = out + 12800000;            // [NM,128]
    float* o_pc  = out + 19200000;            // [NC,2]
    float* o_pm  = out + 19400000;            // [NM,2]
    float* o_rc  = out + 19500000;            // [NC]
    float* o_rm  = out + 19600000;            // [NM]

    // CSR build (shared by both layers)
    k_zero<<<(NC + 255) / 256, 256>>>();
    k_count<<<1024, 256>>>(dst_cm, dst_mc);
    k_scan<0><<<1, 1024>>>();
    k_scan<1><<<1, 1024>>>();
    k_fill<<<1024, 256>>>(src_cm, dst_cm, src_mc, dst_mc);

    // layer 0
    k_aggregate<0, 2, 0><<<(NM * 32 + 255) / 256, 256>>>(x_card);   // mean_m <- x_card
    k_aggregate<1, 2, 0><<<(NC * 32 + 255) / 256, 256>>>(x_merch);  // mean_c <- x_merchant
    k_gemm<0, 0, 1><<<(NM + 31) / 32, 256>>>(x_merch, nullptr, Wl0_cm, Wr0_cm, bl0_cm, NM, 64); // h_m
    k_gemm<1, 0, 2><<<(NC + 31) / 32, 256>>>(x_card, nullptr, Wl0_mc, Wr0_mc, bl0_mc, NC, 64);  // h_c

    // layer 1
    k_aggregate<0, 4, 2><<<(NM * 32 + 255) / 256, 256>>>(nullptr);  // mean_m <- h_c over cm
    k_aggregate<1, 4, 1><<<(NC * 32 + 255) / 256, 256>>>(nullptr);  // mean_c <- h_m over mc
    k_gemm<0, 1, 0><<<(NM + 31) / 32, 256>>>(nullptr, o_hm2, Wl1_cm, Wr1_cm, bl1_cm, NM, 128);  // h_m2
    k_gemm<1, 2, 0><<<(NC + 31) / 32, 256>>>(nullptr, o_hc2, Wl1_mc, Wr1_mc, bl1_mc, NC, 128);  // h_c2

    // heads
    k_head<<<(NC + 31) / 32, 256>>>(o_hc2, NC, cW1c, cb1c, cW2c, cb2c,
                                    rW1, rb1, rW2, rb2, o_pc, o_rc);
    k_head<<<(NM + 31) / 32, 256>>>(o_hm2, NM, cW1m, cb1m, cW2m, cb2m,
                                    rW1, rb1, rW2, rb2, o_pm, o_rm);
}

// round 3
// speedup vs baseline: 1.1247x; 1.1247x over previous
#include <cuda_runtime.h>
#include <math.h>

#define NC 100000
#define NM 50000
#define NE 1000000

// ---------------- scratch (__device__ globals: allocation-free) ----------------
__device__ float g_mean_m[NM * 128];
__device__ float g_mean_c[NC * 128];
__device__ float g_hm[NM * 128];
__device__ float g_hc[NC * 128];
__device__ int   g_cnt_m[NM], g_cnt_c[NC];
__device__ int   g_off_m[NM], g_off_c[NC];
__device__ int   g_cur_m[NM], g_cur_c[NC];
__device__ int   g_tot[2];
__device__ int   g_csr_cm[NE];   // src card ids grouped by merchant dst
__device__ int   g_csr_mc[NE];   // src merchant ids grouped by card dst

// ---------------- packed f32x2 helpers (Blackwell) ----------------
__device__ __forceinline__ unsigned long long pack2(float x) {
    unsigned long long r;
    asm("mov.b64 %0, {%1, %1};" : "=l"(r) : "f"(x));
    return r;
}
__device__ __forceinline__ void ffma2(unsigned long long& d, unsigned long long a,
                                      unsigned long long b) {
    asm("fma.rn.f32x2 %0, %1, %2, %0;" : "+l"(d) : "l"(a), "l"(b));
}
__device__ __forceinline__ float2 unpack2(unsigned long long v) {
    float2 f;
    asm("mov.b64 {%0, %1}, %2;" : "=f"(f.x), "=f"(f.y) : "l"(v));
    return f;
}

// ---------------- CSR build ----------------
__global__ void k_zero() {
    int i = blockIdx.x * blockDim.x + threadIdx.x;
    if (i < NC) { g_cnt_c[i] = 0; g_cur_c[i] = 0; }
    if (i < NM) { g_cnt_m[i] = 0; g_cur_m[i] = 0; }
    if (i < 2) g_tot[i] = 0;
}

__global__ void k_count(const int* __restrict__ dcm, const int* __restrict__ dmc) {
    for (int i = blockIdx.x * blockDim.x + threadIdx.x; i < NE;
         i += gridDim.x * blockDim.x) {
        atomicAdd(&g_cnt_m[dcm[i]], 1);
        atomicAdd(&g_cnt_c[dmc[i]], 1);
    }
}

// parallel segment allocation: each node gets a contiguous chunk; chunk order is
// whatever the per-block atomicAdd on the global cursor decides (order-free CSR).
// WHICH: 0 = merchants, 1 = cards
template <int WHICH>
__global__ __launch_bounds__(256) void k_alloc() {
    const int N = WHICH ? NC : NM;
    const int* __restrict__ cnt = WHICH ? g_cnt_c : g_cnt_m;
    int* __restrict__ off = WHICH ? g_off_c : g_off_m;

    int i = blockIdx.x * 256 + threadIdx.x;
    int t = threadIdx.x;
    int lane = t & 31, wid = t >> 5;

    int c = (i < N) ? cnt[i] : 0;
    // warp inclusive scan
    int v = c;
#pragma unroll
    for (int d = 1; d < 32; d <<= 1) {
        int n = __shfl_up_sync(0xffffffffu, v, d);
        if (lane >= d) v += n;
    }
    __shared__ int wsum[8];
    __shared__ int wbase[8];
    __shared__ int blkbase;
    if (lane == 31) wsum[wid] = v;
    __syncthreads();
    if (t == 0) {
        int run = 0;
#pragma unroll
        for (int w = 0; w < 8; w++) { wbase[w] = run; run += wsum[w]; }
        blkbase = atomicAdd(&g_tot[WHICH], run);
    }
    __syncthreads();
    if (i < N) off[i] = blkbase + wbase[wid] + (v - c);
}

__global__ void k_fill(const int* __restrict__ scm, const int* __restrict__ dcm,
                       const int* __restrict__ smc, const int* __restrict__ dmc) {
    for (int i = blockIdx.x * blockDim.x + threadIdx.x; i < NE;
         i += gridDim.x * blockDim.x) {
        int d = dcm[i];
        int p = g_off_m[d] + atomicAdd(&g_cur_m[d], 1);
        g_csr_cm[p] = scm[i];
        int d2 = dmc[i];
        int p2 = g_off_c[d2] + atomicAdd(&g_cur_c[d2], 1);
        g_csr_mc[p2] = smc[i];
    }
}

// ---------------- gather-style mean aggregation (no float atomics) ----------------
// GRAPH: 0 = cm edges (dst = merchants), 1 = mc edges (dst = cards)
// KVEC:  floats per lane (2 -> K=64, 4 -> K=128)
// XS:    0 -> xext argument, 1 -> g_hm, 2 -> g_hc
template <int GRAPH, int KVEC, int XS>
__global__ void k_aggregate(const float* __restrict__ xext) {
    const int* __restrict__ off = GRAPH ? g_off_c : g_off_m;
    const int* __restrict__ cnt = GRAPH ? g_cnt_c : g_cnt_m;
    const int* __restrict__ csr = GRAPH ? g_csr_mc : g_csr_cm;
    float* __restrict__ mean = GRAPH ? g_mean_c : g_mean_m;
    const int nn = GRAPH ? NC : NM;
    const float* __restrict__ xsrc = (XS == 0) ? xext : (XS == 1 ? g_hm : g_hc);

    int w = (blockIdx.x * blockDim.x + threadIdx.x) >> 5;
    if (w >= nn) return;
    int lane = threadIdx.x & 31;
    int n = cnt[w];
    int b = off[w], e = b + n;

    if (KVEC == 2) {
        float ax = 0.f, ay = 0.f;
        for (int j = b; j < e; j++) {
            int s = csr[j];
            float2 v = ((const float2*)(xsrc + (size_t)s * 64))[lane];
            ax += v.x; ay += v.y;
        }
        float r = 1.f / fmaxf((float)n, 1.f);
        ((float2*)(mean + (size_t)w * 64))[lane] = make_float2(ax * r, ay * r);
    } else {
        float ax = 0.f, ay = 0.f, az = 0.f, aw = 0.f;
        for (int j = b; j < e; j++) {
            int s = csr[j];
            float4 v = ((const float4*)(xsrc + (size_t)s * 128))[lane];
            ax += v.x; ay += v.y; az += v.z; aw += v.w;
        }
        float r = 1.f / fmaxf((float)n, 1.f);
        float4 o;
        o.x = ax * r; o.y = ay * r; o.z = az * r; o.w = aw * r;
        ((float4*)(mean + (size_t)w * 128))[lane] = o;
    }
}

// ---------------- fused SAGE GEMM: out = relu([mean|xdst] @ [Wl;Wr] + b) ------------
// 32 rows x 128 cols per block, 256 threads, 4x4 micro-tile, fma.rn.f32x2 inner loop.
// MSEL: 0 -> g_mean_m, 1 -> g_mean_c
// XSEL: 0 -> xext, 1 -> g_hm, 2 -> g_hc
// OSEL: 0 -> oext, 1 -> g_hm, 2 -> g_hc
template <int MSEL, int XSEL, int OSEL>
__global__ __launch_bounds__(256) void k_gemm(const float* __restrict__ xext,
                                              float* __restrict__ oext,
                                              const float* __restrict__ Wl,
                                              const float* __restrict__ Wr,
                                              const float* __restrict__ bias,
                                              int nrows, int KH) {
    const float* __restrict__ mean = MSEL ? g_mean_c : g_mean_m;
    const float* __restrict__ xdst = (XSEL == 0) ? xext : (XSEL == 1 ? g_hm : g_hc);
    float* __restrict__ out = (OSEL == 0) ? oext : (OSEL == 1 ? g_hm : g_hc);

    __shared__ float Ws[64][128];
    __shared__ float As[64][33];

    int t = threadIdx.x;
    int c0 = (t & 31) * 4;
    int r0 = (t >> 5) * 4;
    int row0 = blockIdx.x * 32;

    unsigned long long acc[4][2];
#pragma unroll
    for (int r = 0; r < 4; r++) { acc[r][0] = 0ull; acc[r][1] = 0ull; }

    int nch = (2 * KH) >> 6;
    for (int ch = 0; ch < nch; ++ch) {
        int kbase = ch * 64;
        const float* Asrc;
        const float* Wsrc;
        int kloc;
        if (kbase < KH) {
            Asrc = mean; kloc = kbase; Wsrc = Wl + (size_t)kbase * 128;
        } else {
            Asrc = xdst; kloc = kbase - KH; Wsrc = Wr + (size_t)(kbase - KH) * 128;
        }
        __syncthreads();
#pragma unroll
        for (int i = 0; i < 8; i++) {  // 2048 float4 -> Ws
            int lin = t + i * 256;
            int k = lin >> 5, c4 = lin & 31;
            *(float4*)&Ws[k][c4 * 4] = *(const float4*)(Wsrc + (size_t)k * 128 + c4 * 4);
        }
#pragma unroll
        for (int i = 0; i < 8; i++) {  // 2048 floats -> As (transposed)
            int lin = t + i * 256;
            int k = lin & 63, r = lin >> 6;
            int row = row0 + r;
            if (row >= nrows) row = nrows - 1;
            As[k][r] = Asrc[(size_t)row * KH + kloc + k];
        }
        __syncthreads();
#pragma unroll 8
        for (int k = 0; k < 64; k++) {
            ulonglong2 w = *(const ulonglong2*)&Ws[k][c0];
#pragma unroll
            for (int r = 0; r < 4; r++) {
                unsigned long long aa = pack2(As[k][r0 + r]);
                ffma2(acc[r][0], aa, w.x);
                ffma2(acc[r][1], aa, w.y);
            }
        }
    }

    float4 b4 = *(const float4*)(bias + c0);
#pragma unroll
    for (int r = 0; r < 4; r++) {
        int row = row0 + r0 + r;
        if (row >= nrows) continue;
        float2 lo = unpack2(acc[r][0]);
        float2 hi = unpack2(acc[r][1]);
        float4 v;
        v.x = fmaxf(lo.x + b4.x, 0.f);
        v.y = fmaxf(lo.y + b4.y, 0.f);
        v.z = fmaxf(hi.x + b4.z, 0.f);
        v.w = fmaxf(hi.y + b4.w, 0.f);
        *(float4*)(out + (size_t)row * 128 + c0) = v;
    }
}

// ---------------- fused heads: class MLP + shared risk scorer ----------------
// phase A: T = relu(h @ [cW1|rW1] + [cb1|rb1])  (32 rows x 128 cols, same micro-kernel)
// phase B: pred = T[:, :64] @ cW2 + cb2 ; risk = sigmoid(T[:, 64:] @ rW2 + rb2)
__global__ __launch_bounds__(256) void k_head(const float* __restrict__ h, int nrows,
                                              const float* __restrict__ cW1,
                                              const float* __restrict__ cb1,
                                              const float* __restrict__ cW2,
                                              const float* __restrict__ cb2,
                                              const float* __restrict__ rW1,
                                              const float* __restrict__ rb1,
                                              const float* __restrict__ rW2,
                                              const float* __restrict__ rb2,
                                              float* __restrict__ pred,
                                              float* __restrict__ risk) {
    __shared__ float Ws[64][128];
    __shared__ float As[64][33];
    __shared__ float Ts[32][132];

    int t = threadIdx.x;
    int c0 = (t & 31) * 4;
    int r0 = (t >> 5) * 4;
    int row0 = blockIdx.x * 32;

    unsigned long long acc[4][2];
#pragma unroll
    for (int r = 0; r < 4; r++) { acc[r][0] = 0ull; acc[r][1] = 0ull; }

    for (int ch = 0; ch < 2; ++ch) {
        int kbase = ch * 64;
        __syncthreads();
#pragma unroll
        for (int i = 0; i < 8; i++) {
            int lin = t + i * 256;
            int k = lin >> 5, c4 = lin & 31;
            const float* src = (c4 < 16) ? (cW1 + (size_t)(kbase + k) * 64 + c4 * 4)
                                         : (rW1 + (size_t)(kbase + k) * 64 + (c4 - 16) * 4);
            *(float4*)&Ws[k][c4 * 4] = *(const float4*)src;
        }
#pragma unroll
        for (int i = 0; i < 8; i++) {
            int lin = t + i * 256;
            int k = lin & 63, r = lin >> 6;
            int row = row0 + r;
            if (row >= nrows) row = nrows - 1;
            As[k][r] = h[(size_t)row * 128 + kbase + k];
        }
        __syncthreads();
#pragma unroll 8
        for (int k = 0; k < 64; k++) {
            ulonglong2 w = *(const ulonglong2*)&Ws[k][c0];
#pragma unroll
            for (int r = 0; r < 4; r++) {
                unsigned long long aa = pack2(As[k][r0 + r]);
                ffma2(acc[r][0], aa, w.x);
                ffma2(acc[r][1], aa, w.y);
            }
        }
    }

    float4 b4 = (c0 < 64) ? *(const float4*)(cb1 + c0) : *(const float4*)(rb1 + c0 - 64);
#pragma unroll
    for (int r = 0; r < 4; r++) {
        float2 lo = unpack2(acc[r][0]);
        float2 hi = unpack2(acc[r][1]);
        float4 v;
        v.x = fmaxf(lo.x + b4.x, 0.f);
        v.y = fmaxf(lo.y + b4.y, 0.f);
        v.z = fmaxf(hi.x + b4.z, 0.f);
        v.w = fmaxf(hi.y + b4.w, 0.f);
        *(float4*)&Ts[r0 + r][c0] = v;
    }
    __syncthreads();

    int wid = t >> 5, lane = t & 31;
    float w00 = cW2[lane * 2], w01 = cW2[lane * 2 + 1];
    float w10 = cW2[(lane + 32) * 2], w11 = cW2[(lane + 32) * 2 + 1];
    float rw0 = rW2[lane], rw1 = rW2[lane + 32];
    for (int rr = wid; rr < 32; rr += 8) {
        int row = row0 + rr;
        float t1a = Ts[rr][lane], t1b = Ts[rr][lane + 32];
        float t2a = Ts[rr][64 + lane], t2b = Ts[rr][96 + lane];
        float p0 = t1a * w00 + t1b * w10;
        float p1 = t1a * w01 + t1b * w11;
        float rk = t2a * rw0 + t2b * rw1;
#pragma unroll
        for (int d = 16; d; d >>= 1) {
            p0 += __shfl_xor_sync(0xffffffffu, p0, d);
            p1 += __shfl_xor_sync(0xffffffffu, p1, d);
            rk += __shfl_xor_sync(0xffffffffu, rk, d);
        }
        if (lane == 0 && row < nrows) {
            pred[(size_t)row * 2 + 0] = p0 + cb2[0];
            pred[(size_t)row * 2 + 1] = p1 + cb2[1];
            float x = rk + rb2[0];
            risk[row] = 1.f / (1.f + __expf(-x));
        }
    }
}

// ---------------- launcher ----------------
extern "C" void kernel_launch(void* const* d_in, const int* in_sizes, int n_in,
                              void* d_out, int out_size) {
    const float* x_card  = (const float*)d_in[0];
    const float* x_merch = (const float*)d_in[1];
    const int* src_cm = (const int*)d_in[2];
    const int* dst_cm = (const int*)d_in[3];
    const int* src_mc = (const int*)d_in[4];
    const int* dst_mc = (const int*)d_in[5];
    const float* Wl0_cm = (const float*)d_in[6];
    const float* bl0_cm = (const float*)d_in[7];
    const float* Wr0_cm = (const float*)d_in[8];
    const float* Wl0_mc = (const float*)d_in[9];
    const float* bl0_mc = (const float*)d_in[10];
    const float* Wr0_mc = (const float*)d_in[11];
    const float* Wl1_cm = (const float*)d_in[12];
    const float* bl1_cm = (const float*)d_in[13];
    const float* Wr1_cm = (const float*)d_in[14];
    const float* Wl1_mc = (const float*)d_in[15];
    const float* bl1_mc = (const float*)d_in[16];
    const float* Wr1_mc = (const float*)d_in[17];
    const float* cW1c = (const float*)d_in[18];
    const float* cb1c = (const float*)d_in[19];
    const float* cW2c = (const float*)d_in[20];
    const float* cb2c = (const float*)d_in[21];
    const float* cW1m = (const float*)d_in[22];
    const float* cb1m = (const float*)d_in[23];
    const float* cW2m = (const float*)d_in[24];
    const float* cb2m = (const float*)d_in[25];
    const float* rW1 = (const float*)d_in[26];
    const float* rb1 = (const float*)d_in[27];
    const float* rW2 = (const float*)d_in[28];
    const float* rb2 = (const float*)d_in[29];

    float* out = (float*)d_out;
    float* o_hc2 = out;                       // [NC,128]
    float* o_hm2 = out + 12800000;            // [NM,128]
    float* o_pc  = out + 19200000;            // [NC,2]
    float* o_pm  = out + 19400000;            // [NM,2]
    float* o_rc  = out + 19500000;            // [NC]
    float* o_rm  = out + 19600000;            // [NM]

    // CSR build (shared by both layers) — parallel chunk allocation, no serial scan
    k_zero<<<(NC + 255) / 256, 256>>>();
    k_count<<<1024, 256>>>(dst_cm, dst_mc);
    k_alloc<0><<<(NM + 255) / 256, 256>>>();
    k_alloc<1><<<(NC + 255) / 256, 256>>>();
    k_fill<<<1024, 256>>>(src_cm, dst_cm, src_mc, dst_mc);

    // layer 0
    k_aggregate<0, 2, 0><<<(NM * 32 + 255) / 256, 256>>>(x_card);   // mean_m <- x_card
    k_aggregate<1, 2, 0><<<(NC * 32 + 255) / 256, 256>>>(x_merch);  // mean_c <- x_merchant
    k_gemm<0, 0, 1><<<(NM + 31) / 32, 256>>>(x_merch, nullptr, Wl0_cm, Wr0_cm, bl0_cm, NM, 64); // h_m
    k_gemm<1, 0, 2><<<(NC + 31) / 32, 256>>>(x_card, nullptr, Wl0_mc, Wr0_mc, bl0_mc, NC, 64);  // h_c

    // layer 1
    k_aggregate<0, 4, 2><<<(NM * 32 + 255) / 256, 256>>>(nullptr);  // mean_m <- h_c over cm
    k_aggregate<1, 4, 1><<<(NC * 32 + 255) / 256, 256>>>(nullptr);  // mean_c <- h_m over mc
    k_gemm<0, 1, 0><<<(NM + 31) / 32, 256>>>(nullptr, o_hm2, Wl1_cm, Wr1_cm, bl1_cm, NM, 128);  // h_m2
    k_gemm<1, 2, 0><<<(NC + 31) / 32, 256>>>(nullptr, o_hc2, Wl1_mc, Wr1_mc, bl1_mc, NC, 128);  // h_c2

    // heads
    k_head<<<(NC + 31) / 32, 256>>>(o_hc2, NC, cW1c, cb1c, cW2c, cb2c,
                                    rW1, rb1, rW2, rb2, o_pc, o_rc);
    k_head<<<(NM + 31) / 32, 256>>>(o_hm2, NM, cW1m, cb1m, cW2m, cb2m,
                                    rW1, rb1, rW2, rb2, o_pm, o_rm);
}

// round 7
// speedup vs baseline: 1.3025x; 1.1581x over previous
#include <cuda_runtime.h>
#include <cuda_bf16.h>
#include <math.h>
#include <stdint.h>

#define NC 100000
#define NM 50000
#define NE 1000000

// ---------------- scratch (__device__ globals: allocation-free) ----------------
__device__ float g_mean_m[NM * 128];
__device__ float g_mean_c[NC * 128];
__device__ float g_hm[NM * 128];
__device__ float g_hc[NC * 128];
__device__ int   g_cnt_m[NM], g_cnt_c[NC];
__device__ int   g_off_m[NM], g_off_c[NC];
__device__ int   g_cur_m[NM], g_cur_c[NC];
__device__ int   g_tot[2];
__device__ int   g_csr_cm[NE];
__device__ int   g_csr_mc[NE];

// transposed, bf16-split weights: [hi/lo][n*KTOT + k]
__device__ __nv_bfloat16 g_b0cm[2][128 * 128];
__device__ __nv_bfloat16 g_b0mc[2][128 * 128];
__device__ __nv_bfloat16 g_b1cm[2][128 * 256];
__device__ __nv_bfloat16 g_b1mc[2][128 * 256];
__device__ __nv_bfloat16 g_bhc[2][128 * 128];
__device__ __nv_bfloat16 g_bhm[2][128 * 128];

// ---------------- baseline-PTX tensor-core helpers (compute_103-safe) ----------------
static __device__ __forceinline__ uint32_t smem_u32(const void* p) {
    uint32_t a;
    asm("{ .reg .u64 t; cvta.to.shared.u64 t, %1; cvt.u32.u64 %0, t; }" : "=r"(a) : "l"(p));
    return a;
}
static __device__ __forceinline__ void ldsm4(uint32_t* r, uint32_t addr) {
    asm volatile("ldmatrix.sync.aligned.m8n8.x4.shared.b16 {%0,%1,%2,%3}, [%4];"
                 : "=r"(r[0]), "=r"(r[1]), "=r"(r[2]), "=r"(r[3]) : "r"(addr));
}
static __device__ __forceinline__ void mma_bf16(float* c, const uint32_t* a,
                                                uint32_t b0, uint32_t b1) {
    asm volatile("mma.sync.aligned.m16n8k16.row.col.f32.bf16.bf16.f32 "
                 "{%0,%1,%2,%3}, {%4,%5,%6,%7}, {%8,%9}, {%0,%1,%2,%3};"
                 : "+f"(c[0]), "+f"(c[1]), "+f"(c[2]), "+f"(c[3])
                 : "r"(a[0]), "r"(a[1]), "r"(a[2]), "r"(a[3]), "r"(b0), "r"(b1));
}

// ---------------- CSR build ----------------
__global__ void k_zero() {
    int i = blockIdx.x * blockDim.x + threadIdx.x;
    if (i < NC) { g_cnt_c[i] = 0; g_cur_c[i] = 0; }
    if (i < NM) { g_cnt_m[i] = 0; g_cur_m[i] = 0; }
    if (i < 2) g_tot[i] = 0;
}

__global__ void k_count(const int* __restrict__ dcm, const int* __restrict__ dmc) {
    for (int i = blockIdx.x * blockDim.x + threadIdx.x; i < NE; i += gridDim.x * blockDim.x) {
        atomicAdd(&g_cnt_m[dcm[i]], 1);
        atomicAdd(&g_cnt_c[dmc[i]], 1);
    }
}

template <int WHICH>
__global__ __launch_bounds__(256) void k_alloc() {
    const int N = WHICH ? NC : NM;
    const int* __restrict__ cnt = WHICH ? g_cnt_c : g_cnt_m;
    int* __restrict__ off = WHICH ? g_off_c : g_off_m;
    int i = blockIdx.x * 256 + threadIdx.x;
    int t = threadIdx.x, lane = t & 31, wid = t >> 5;
    int c = (i < N) ? cnt[i] : 0;
    int v = c;
#pragma unroll
    for (int d = 1; d < 32; d <<= 1) {
        int n = __shfl_up_sync(0xffffffffu, v, d);
        if (lane >= d) v += n;
    }
    __shared__ int wsum[8], wbase[8], blkbase;
    if (lane == 31) wsum[wid] = v;
    __syncthreads();
    if (t == 0) {
        int run = 0;
#pragma unroll
        for (int w = 0; w < 8; w++) { wbase[w] = run; run += wsum[w]; }
        blkbase = atomicAdd(&g_tot[WHICH], run);
    }
    __syncthreads();
    if (i < N) off[i] = blkbase + wbase[wid] + (v - c);
}

__global__ void k_fill(const int* __restrict__ scm, const int* __restrict__ dcm,
                       const int* __restrict__ smc, const int* __restrict__ dmc) {
    for (int i = blockIdx.x * blockDim.x + threadIdx.x; i < NE; i += gridDim.x * blockDim.x) {
        int d = dcm[i];
        int p = g_off_m[d] + atomicAdd(&g_cur_m[d], 1);
        g_csr_cm[p] = scm[i];
        int d2 = dmc[i];
        int p2 = g_off_c[d2] + atomicAdd(&g_cur_c[d2], 1);
        g_csr_mc[p2] = smc[i];
    }
}

// ---------------- weight prep: transpose + bf16 split ----------------
static __device__ __forceinline__ void cvt_split(float v, __nv_bfloat16* hi, __nv_bfloat16* lo, int pos) {
    __nv_bfloat16 h = __float2bfloat16(v);
    hi[pos] = h;
    lo[pos] = __float2bfloat16(v - __bfloat162float(h));
}

__global__ __launch_bounds__(256) void k_prep(
    const float* Wl0cm, const float* Wr0cm, const float* Wl0mc, const float* Wr0mc,
    const float* Wl1cm, const float* Wr1cm, const float* Wl1mc, const float* Wr1mc,
    const float* cW1c, const float* cW1m, const float* rW1) {
    int i = blockIdx.x * 256 + threadIdx.x;
    if (i < 16384) {
        int k = i >> 7, n = i & 127;
        float v = (k < 64) ? Wl0cm[k * 128 + n] : Wr0cm[(k - 64) * 128 + n];
        cvt_split(v, g_b0cm[0], g_b0cm[1], n * 128 + k);
    } else if (i < 32768) {
        int j = i - 16384; int k = j >> 7, n = j & 127;
        float v = (k < 64) ? Wl0mc[k * 128 + n] : Wr0mc[(k - 64) * 128 + n];
        cvt_split(v, g_b0mc[0], g_b0mc[1], n * 128 + k);
    } else if (i < 65536) {
        int j = i - 32768; int k = j >> 7, n = j & 127;
        float v = (k < 128) ? Wl1cm[k * 128 + n] : Wr1cm[(k - 128) * 128 + n];
        cvt_split(v, g_b1cm[0], g_b1cm[1], n * 256 + k);
    } else if (i < 98304) {
        int j = i - 65536; int k = j >> 7, n = j & 127;
        float v = (k < 128) ? Wl1mc[k * 128 + n] : Wr1mc[(k - 128) * 128 + n];
        cvt_split(v, g_b1mc[0], g_b1mc[1], n * 256 + k);
    } else if (i < 114688) {
        int j = i - 98304; int k = j >> 7, n = j & 127;
        float v = (n < 64) ? cW1c[k * 64 + n] : rW1[k * 64 + (n - 64)];
        cvt_split(v, g_bhc[0], g_bhc[1], n * 128 + k);
    } else if (i < 131072) {
        int j = i - 114688; int k = j >> 7, n = j & 127;
        float v = (n < 64) ? cW1m[k * 64 + n] : rW1[k * 64 + (n - 64)];
        cvt_split(v, g_bhm[0], g_bhm[1], n * 128 + k);
    }
}

// ---------------- gather-style mean aggregation ----------------
template <int GRAPH, int KVEC, int XS>
__global__ void k_aggregate(const float* __restrict__ xext) {
    const int* __restrict__ off = GRAPH ? g_off_c : g_off_m;
    const int* __restrict__ cnt = GRAPH ? g_cnt_c : g_cnt_m;
    const int* __restrict__ csr = GRAPH ? g_csr_mc : g_csr_cm;
    float* __restrict__ mean = GRAPH ? g_mean_c : g_mean_m;
    const int nn = GRAPH ? NC : NM;
    const float* __restrict__ xsrc = (XS == 0) ? xext : (XS == 1 ? g_hm : g_hc);

    int w = (blockIdx.x * blockDim.x + threadIdx.x) >> 5;
    if (w >= nn) return;
    int lane = threadIdx.x & 31;
    int n = cnt[w];
    int b = off[w], e = b + n;

    if (KVEC == 2) {
        float ax = 0.f, ay = 0.f;
        for (int j = b; j < e; j++) {
            int s = csr[j];
            float2 v = ((const float2*)(xsrc + (size_t)s * 64))[lane];
            ax += v.x; ay += v.y;
        }
        float r = 1.f / fmaxf((float)n, 1.f);
        ((float2*)(mean + (size_t)w * 64))[lane] = make_float2(ax * r, ay * r);
    } else {
        float ax = 0.f, ay = 0.f, az = 0.f, aw = 0.f;
        for (int j = b; j < e; j++) {
            int s = csr[j];
            float4 v = ((const float4*)(xsrc + (size_t)s * 128))[lane];
            ax += v.x; ay += v.y; az += v.z; aw += v.w;
        }
        float r = 1.f / fmaxf((float)n, 1.f);
        float4 o;
        o.x = ax * r; o.y = ay * r; o.z = az * r; o.w = aw * r;
        ((float4*)(mean + (size_t)w * 128))[lane] = o;
    }
}

// ---------------- bf16-split tensor-core GEMM (mma.sync, baseline PTX) ----------------
// C[128 rows x 128 cols] per block; 8 warps as 4(row) x 2(col); warp tile 32x64.
// EPI: 0 = SAGE relu(D+bias)->out ; 1 = heads (class + risk)
// ASEL: A source for k<KH: 0=g_mean_m, 1=g_mean_c, 2=xext
// XSEL: A source for k>=KH: 0=xext, 1=g_hm, 2=g_hc
// OSEL (EPI=0): 0=oext, 1=g_hm, 2=g_hc
// WSEL: weight table (selected in DEVICE code; host must not touch __device__ globals)
template <int EPI, int ASEL, int XSEL, int OSEL, int WSEL>
__global__ __launch_bounds__(256, 2) void k_mma(
    const float* __restrict__ xext, float* __restrict__ oext,
    const float* __restrict__ bias, const float* __restrict__ hb2,
    const float* __restrict__ cW2, const float* __restrict__ cb2,
    const float* __restrict__ rW2, const float* __restrict__ rb2,
    float* __restrict__ pred, float* __restrict__ risk,
    int nrows, int KH, int KTOT) {
    __shared__ __align__(16) __nv_bfloat16 Ah[128][40], Al[128][40], Bh[128][40], Bl[128][40];
    __shared__ float b1s[128];
    __shared__ float cw2s[128];
    __shared__ float rw2s[64];
    __shared__ float cb2s[2], rb2s[1];

    const __nv_bfloat16* bt_hi =
        (WSEL == 0) ? g_b0cm[0] : (WSEL == 1) ? g_b0mc[0] : (WSEL == 2) ? g_b1cm[0]
        : (WSEL == 3) ? g_b1mc[0] : (WSEL == 4) ? g_bhc[0] : g_bhm[0];
    const __nv_bfloat16* bt_lo =
        (WSEL == 0) ? g_b0cm[1] : (WSEL == 1) ? g_b0mc[1] : (WSEL == 2) ? g_b1cm[1]
        : (WSEL == 3) ? g_b1mc[1] : (WSEL == 4) ? g_bhc[1] : g_bhm[1];

    const float* a0 = (ASEL == 0) ? g_mean_m : (ASEL == 1 ? g_mean_c : xext);
    const float* a1 = (XSEL == 0) ? xext : (XSEL == 1 ? g_hm : g_hc);
    float* out = (OSEL == 0) ? oext : (OSEL == 1 ? g_hm : g_hc);

    int t = threadIdx.x;
    int wid = t >> 5, lane = t & 31;
    int wr = wid >> 1, wc = wid & 1;
    int row0 = blockIdx.x * 128;

    if (EPI == 0) {
        if (t < 128) b1s[t] = bias[t];
    } else {
        if (t < 64) { b1s[t] = bias[t]; b1s[64 + t] = hb2[t]; rw2s[t] = rW2[t]; }
        if (t >= 128 && t < 256) cw2s[t - 128] = cW2[t - 128];
        if (t == 64) { cb2s[0] = cb2[0]; cb2s[1] = cb2[1]; rb2s[0] = rb2[0]; }
    }

    float acc[2][8][4];
#pragma unroll
    for (int m = 0; m < 2; m++)
#pragma unroll
        for (int n = 0; n < 8; n++)
#pragma unroll
            for (int j = 0; j < 4; j++) acc[m][n][j] = 0.f;

    int lrow = t >> 1;
    int kq = (t & 1) * 16;
    int grow = row0 + lrow;
    if (grow >= nrows) grow = nrows - 1;

    int nch = KTOT >> 5;
    for (int ch = 0; ch < nch; ch++) {
        int gk = ch * 32;
        __syncthreads();
        // ---- A: 128 rows x 32 k fp32 -> split hi/lo bf16 into smem ----
        {
            const float* srcp;
            if (gk < KH) srcp = a0 + (size_t)grow * KH + gk + kq;
            else         srcp = a1 + (size_t)grow * KH + (gk - KH) + kq;
#pragma unroll
            for (int j = 0; j < 4; j++) {
                float4 v = *(const float4*)(srcp + j * 4);
                __nv_bfloat162 h01 = __float22bfloat162_rn(make_float2(v.x, v.y));
                __nv_bfloat162 h23 = __float22bfloat162_rn(make_float2(v.z, v.w));
                __nv_bfloat162 l01 = __float22bfloat162_rn(make_float2(
                    v.x - __bfloat162float(h01.x), v.y - __bfloat162float(h01.y)));
                __nv_bfloat162 l23 = __float22bfloat162_rn(make_float2(
                    v.z - __bfloat162float(h23.x), v.w - __bfloat162float(h23.y)));
                uint2 uh = make_uint2(*reinterpret_cast<unsigned*>(&h01),
                                      *reinterpret_cast<unsigned*>(&h23));
                uint2 ul = make_uint2(*reinterpret_cast<unsigned*>(&l01),
                                      *reinterpret_cast<unsigned*>(&l23));
                *(uint2*)&Ah[lrow][kq + j * 4] = uh;
                *(uint2*)&Al[lrow][kq + j * 4] = ul;
            }
        }
        // ---- B: prepped bf16 [n][KTOT] -> smem ----
        {
            const __nv_bfloat16* sh = bt_hi + (size_t)lrow * KTOT + gk + kq;
            const __nv_bfloat16* sl = bt_lo + (size_t)lrow * KTOT + gk + kq;
            uint4 uh0 = ((const uint4*)sh)[0], uh1 = ((const uint4*)sh)[1];
            uint4 ul0 = ((const uint4*)sl)[0], ul1 = ((const uint4*)sl)[1];
            *(uint4*)&Bh[lrow][kq] = uh0; *(uint4*)&Bh[lrow][kq + 8] = uh1;
            *(uint4*)&Bl[lrow][kq] = ul0; *(uint4*)&Bl[lrow][kq + 8] = ul1;
        }
        __syncthreads();

        int lr = lane & 15, lk = (lane >> 4) * 8;
#pragma unroll
        for (int kt = 0; kt < 2; kt++) {
            uint32_t a_h[2][4], a_l[2][4];
#pragma unroll
            for (int mt = 0; mt < 2; mt++) {
                ldsm4(a_h[mt], smem_u32(&Ah[wr * 32 + mt * 16 + lr][kt * 16 + lk]));
                ldsm4(a_l[mt], smem_u32(&Al[wr * 32 + mt * 16 + lr][kt * 16 + lk]));
            }
#pragma unroll
            for (int nb = 0; nb < 4; nb++) {
                uint32_t bh[4], bl[4];
                ldsm4(bh, smem_u32(&Bh[wc * 64 + nb * 16 + lr][kt * 16 + lk]));
                ldsm4(bl, smem_u32(&Bl[wc * 64 + nb * 16 + lr][kt * 16 + lk]));
#pragma unroll
                for (int sn = 0; sn < 2; sn++) {
#pragma unroll
                    for (int mt = 0; mt < 2; mt++) {
                        float* c = acc[mt][nb * 2 + sn];
                        mma_bf16(c, a_h[mt], bh[sn], bh[sn + 2]);
                        mma_bf16(c, a_h[mt], bl[sn], bl[sn + 2]);
                        mma_bf16(c, a_l[mt], bh[sn], bh[sn + 2]);
                    }
                }
            }
        }
    }

    int q = lane & 3, rq = lane >> 2;
    if (EPI == 0) {
#pragma unroll
        for (int mt = 0; mt < 2; mt++) {
#pragma unroll
            for (int nf = 0; nf < 8; nf++) {
                int gc = wc * 64 + (nf >> 1) * 16 + (nf & 1) * 8 + q * 2;
                float b0 = b1s[gc], b1 = b1s[gc + 1];
                int r1 = row0 + wr * 32 + mt * 16 + rq;
                int r2 = r1 + 8;
                if (r1 < nrows) {
                    float2 v = make_float2(fmaxf(acc[mt][nf][0] + b0, 0.f),
                                           fmaxf(acc[mt][nf][1] + b1, 0.f));
                    *(float2*)&out[(size_t)r1 * 128 + gc] = v;
                }
                if (r2 < nrows) {
                    float2 v = make_float2(fmaxf(acc[mt][nf][2] + b0, 0.f),
                                           fmaxf(acc[mt][nf][3] + b1, 0.f));
                    *(float2*)&out[(size_t)r2 * 128 + gc] = v;
                }
            }
        }
    } else {
        // heads: wc=0 -> class (cols 0..63), wc=1 -> risk (cols 64..127)
#pragma unroll
        for (int mt = 0; mt < 2; mt++) {
#pragma unroll
            for (int h = 0; h < 2; h++) {
                int grow2 = row0 + wr * 32 + mt * 16 + h * 8 + rq;
                float p0 = 0.f, p1 = 0.f, rk = 0.f;
#pragma unroll
                for (int nf = 0; nf < 8; nf++) {
                    int gc = wc * 64 + (nf >> 1) * 16 + (nf & 1) * 8 + q * 2;
                    float T0 = fmaxf(acc[mt][nf][h * 2 + 0] + b1s[gc], 0.f);
                    float T1 = fmaxf(acc[mt][nf][h * 2 + 1] + b1s[gc + 1], 0.f);
                    if (wc == 0) {
                        p0 += T0 * cw2s[gc * 2] + T1 * cw2s[(gc + 1) * 2];
                        p1 += T0 * cw2s[gc * 2 + 1] + T1 * cw2s[(gc + 1) * 2 + 1];
                    } else {
                        rk += T0 * rw2s[gc - 64] + T1 * rw2s[gc + 1 - 64];
                    }
                }
                if (wc == 0) {
                    p0 += __shfl_xor_sync(0xffffffffu, p0, 1);
                    p0 += __shfl_xor_sync(0xffffffffu, p0, 2);
                    p1 += __shfl_xor_sync(0xffffffffu, p1, 1);
                    p1 += __shfl_xor_sync(0xffffffffu, p1, 2);
                    if (q == 0 && grow2 < nrows) {
                        pred[(size_t)grow2 * 2 + 0] = p0 + cb2s[0];
                        pred[(size_t)grow2 * 2 + 1] = p1 + cb2s[1];
                    }
                } else {
                    rk += __shfl_xor_sync(0xffffffffu, rk, 1);
                    rk += __shfl_xor_sync(0xffffffffu, rk, 2);
                    if (q == 0 && grow2 < nrows) {
                        float x = rk + rb2s[0];
                        risk[grow2] = 1.f / (1.f + __expf(-x));
                    }
                }
            }
        }
    }
}

// ---------------- launcher ----------------
extern "C" void kernel_launch(void* const* d_in, const int* in_sizes, int n_in,
                              void* d_out, int out_size) {
    const float* x_card  = (const float*)d_in[0];
    const float* x_merch = (const float*)d_in[1];
    const int* src_cm = (const int*)d_in[2];
    const int* dst_cm = (const int*)d_in[3];
    const int* src_mc = (const int*)d_in[4];
    const int* dst_mc = (const int*)d_in[5];
    const float* Wl0_cm = (const float*)d_in[6];
    const float* bl0_cm = (const float*)d_in[7];
    const float* Wr0_cm = (const float*)d_in[8];
    const float* Wl0_mc = (const float*)d_in[9];
    const float* bl0_mc = (const float*)d_in[10];
    const float* Wr0_mc = (const float*)d_in[11];
    const float* Wl1_cm = (const float*)d_in[12];
    const float* bl1_cm = (const float*)d_in[13];
    const float* Wr1_cm = (const float*)d_in[14];
    const float* Wl1_mc = (const float*)d_in[15];
    const float* bl1_mc = (const float*)d_in[16];
    const float* Wr1_mc = (const float*)d_in[17];
    const float* cW1c = (const float*)d_in[18];
    const float* cb1c = (const float*)d_in[19];
    const float* cW2c = (const float*)d_in[20];
    const float* cb2c = (const float*)d_in[21];
    const float* cW1m = (const float*)d_in[22];
    const float* cb1m = (const float*)d_in[23];
    const float* cW2m = (const float*)d_in[24];
    const float* cb2m = (const float*)d_in[25];
    const float* rW1 = (const float*)d_in[26];
    const float* rb1 = (const float*)d_in[27];
    const float* rW2 = (const float*)d_in[28];
    const float* rb2 = (const float*)d_in[29];

    float* out = (float*)d_out;
    float* o_hc2 = out;
    float* o_hm2 = out + 12800000;
    float* o_pc  = out + 19200000;
    float* o_pm  = out + 19400000;
    float* o_rc  = out + 19500000;
    float* o_rm  = out + 19600000;

    // CSR build
    k_zero<<<(NC + 255) / 256, 256>>>();
    k_count<<<1024, 256>>>(dst_cm, dst_mc);
    k_alloc<0><<<(NM + 255) / 256, 256>>>();
    k_alloc<1><<<(NC + 255) / 256, 256>>>();
    k_fill<<<1024, 256>>>(src_cm, dst_cm, src_mc, dst_mc);

    // weight prep (transpose + bf16 split)
    k_prep<<<512, 256>>>(Wl0_cm, Wr0_cm, Wl0_mc, Wr0_mc, Wl1_cm, Wr1_cm, Wl1_mc, Wr1_mc,
                         cW1c, cW1m, rW1);

    // layer 0
    k_aggregate<0, 2, 0><<<(NM * 32 + 255) / 256, 256>>>(x_card);
    k_aggregate<1, 2, 0><<<(NC * 32 + 255) / 256, 256>>>(x_merch);
    k_mma<0, 0, 0, 1, 0><<<(NM + 127) / 128, 256>>>(
        x_merch, nullptr, bl0_cm,
        nullptr, nullptr, nullptr, nullptr, nullptr, nullptr, nullptr, NM, 64, 128);
    k_mma<0, 1, 0, 2, 1><<<(NC + 127) / 128, 256>>>(
        x_card, nullptr, bl0_mc,
        nullptr, nullptr, nullptr, nullptr, nullptr, nullptr, nullptr, NC, 64, 128);

    // layer 1
    k_aggregate<0, 4, 2><<<(NM * 32 + 255) / 256, 256>>>(nullptr);
    k_aggregate<1, 4, 1><<<(NC * 32 + 255) / 256, 256>>>(nullptr);
    k_mma<0, 0, 1, 0, 2><<<(NM + 127) / 128, 256>>>(
        nullptr, o_hm2, bl1_cm,
        nullptr, nullptr, nullptr, nullptr, nullptr, nullptr, nullptr, NM, 128, 256);
    k_mma<0, 1, 2, 0, 3><<<(NC + 127) / 128, 256>>>(
        nullptr, o_hc2, bl1_mc,
        nullptr, nullptr, nullptr, nullptr, nullptr, nullptr, nullptr, NC, 128, 256);

    // heads
    k_mma<1, 2, 0, 0, 4><<<(NC + 127) / 128, 256>>>(
        o_hc2, nullptr, cb1c,
        rb1, cW2c, cb2c, rW2, rb2, o_pc, o_rc, NC, 128, 128);
    k_mma<1, 2, 0, 0, 5><<<(NM + 127) / 128, 256>>>(
        o_hm2, nullptr, cb1m,
        rb1, cW2m, cb2m, rW2, rb2, o_pm, o_rm, NM, 128, 128);
}

// round 9
// speedup vs baseline: 1.8678x; 1.4340x over previous
#include <cuda_runtime.h>
#include <cuda_bf16.h>
#include <math.h>
#include <stdint.h>

#define NC 100000
#define NM 50000
#define NE 1000000

// ---------------- scratch (__device__ globals: allocation-free) ----------------
__device__ float g_mean_m[NM * 128];
__device__ float g_mean_c[NC * 128];
__device__ float g_hm[NM * 128];
__device__ float g_hc[NC * 128];
__device__ int   g_cnt_m[NM], g_cnt_c[NC];
__device__ int   g_off_m[NM], g_off_c[NC];
__device__ int   g_cur_m[NM], g_cur_c[NC];
__device__ int   g_tot[2];
__device__ int   g_csr_cm[NE];
__device__ int   g_csr_mc[NE];

// transposed, bf16-split weights: [hi/lo][n*KTOT + k]
__device__ __nv_bfloat16 g_b0cm[2][128 * 128];
__device__ __nv_bfloat16 g_b0mc[2][128 * 128];
__device__ __nv_bfloat16 g_b1cm[2][128 * 256];
__device__ __nv_bfloat16 g_b1mc[2][128 * 256];
__device__ __nv_bfloat16 g_bhc[2][128 * 128];
__device__ __nv_bfloat16 g_bhm[2][128 * 128];

// ---------------- baseline-PTX tensor-core helpers (compute_103-safe) ----------------
static __device__ __forceinline__ uint32_t smem_u32(const void* p) {
    uint32_t a;
    asm("{ .reg .u64 t; cvta.to.shared.u64 t, %1; cvt.u32.u64 %0, t; }" : "=r"(a) : "l"(p));
    return a;
}
static __device__ __forceinline__ void ldsm4(uint32_t* r, uint32_t addr) {
    asm volatile("ldmatrix.sync.aligned.m8n8.x4.shared.b16 {%0,%1,%2,%3}, [%4];"
                 : "=r"(r[0]), "=r"(r[1]), "=r"(r[2]), "=r"(r[3]) : "r"(addr));
}
static __device__ __forceinline__ void mma_bf16(float* c, const uint32_t* a,
                                                uint32_t b0, uint32_t b1) {
    asm volatile("mma.sync.aligned.m16n8k16.row.col.f32.bf16.bf16.f32 "
                 "{%0,%1,%2,%3}, {%4,%5,%6,%7}, {%8,%9}, {%0,%1,%2,%3};"
                 : "+f"(c[0]), "+f"(c[1]), "+f"(c[2]), "+f"(c[3])
                 : "r"(a[0]), "r"(a[1]), "r"(a[2]), "r"(a[3]), "r"(b0), "r"(b1));
}

// ---------------- CSR build ----------------
__global__ void k_zero() {
    int i = blockIdx.x * blockDim.x + threadIdx.x;
    if (i < NC) { g_cnt_c[i] = 0; g_cur_c[i] = 0; }
    if (i < NM) { g_cnt_m[i] = 0; g_cur_m[i] = 0; }
    if (i < 2) g_tot[i] = 0;
}

__global__ void k_count(const int* __restrict__ dcm, const int* __restrict__ dmc) {
    for (int i = blockIdx.x * blockDim.x + threadIdx.x; i < NE; i += gridDim.x * blockDim.x) {
        atomicAdd(&g_cnt_m[dcm[i]], 1);
        atomicAdd(&g_cnt_c[dmc[i]], 1);
    }
}

template <int WHICH>
__global__ __launch_bounds__(256) void k_alloc() {
    const int N = WHICH ? NC : NM;
    const int* __restrict__ cnt = WHICH ? g_cnt_c : g_cnt_m;
    int* __restrict__ off = WHICH ? g_off_c : g_off_m;
    int i = blockIdx.x * 256 + threadIdx.x;
    int t = threadIdx.x, lane = t & 31, wid = t >> 5;
    int c = (i < N) ? cnt[i] : 0;
    int v = c;
#pragma unroll
    for (int d = 1; d < 32; d <<= 1) {
        int n = __shfl_up_sync(0xffffffffu, v, d);
        if (lane >= d) v += n;
    }
    __shared__ int wsum[8], wbase[8], blkbase;
    if (lane == 31) wsum[wid] = v;
    __syncthreads();
    if (t == 0) {
        int run = 0;
#pragma unroll
        for (int w = 0; w < 8; w++) { wbase[w] = run; run += wsum[w]; }
        blkbase = atomicAdd(&g_tot[WHICH], run);
    }
    __syncthreads();
    if (i < N) off[i] = blkbase + wbase[wid] + (v - c);
}

__global__ void k_fill(const int* __restrict__ scm, const int* __restrict__ dcm,
                       const int* __restrict__ smc, const int* __restrict__ dmc) {
    for (int i = blockIdx.x * blockDim.x + threadIdx.x; i < NE; i += gridDim.x * blockDim.x) {
        int d = dcm[i];
        int p = g_off_m[d] + atomicAdd(&g_cur_m[d], 1);
        g_csr_cm[p] = scm[i];
        int d2 = dmc[i];
        int p2 = g_off_c[d2] + atomicAdd(&g_cur_c[d2], 1);
        g_csr_mc[p2] = smc[i];
    }
}

// ---------------- weight prep: transpose + bf16 split ----------------
static __device__ __forceinline__ void cvt_split(float v, __nv_bfloat16* hi, __nv_bfloat16* lo, int pos) {
    __nv_bfloat16 h = __float2bfloat16(v);
    hi[pos] = h;
    lo[pos] = __float2bfloat16(v - __bfloat162float(h));
}

__global__ __launch_bounds__(256) void k_prep(
    const float* Wl0cm, const float* Wr0cm, const float* Wl0mc, const float* Wr0mc,
    const float* Wl1cm, const float* Wr1cm, const float* Wl1mc, const float* Wr1mc,
    const float* cW1c, const float* cW1m, const float* rW1) {
    int i = blockIdx.x * 256 + threadIdx.x;
    if (i < 16384) {
        int k = i >> 7, n = i & 127;
        float v = (k < 64) ? Wl0cm[k * 128 + n] : Wr0cm[(k - 64) * 128 + n];
        cvt_split(v, g_b0cm[0], g_b0cm[1], n * 128 + k);
    } else if (i < 32768) {
        int j = i - 16384; int k = j >> 7, n = j & 127;
        float v = (k < 64) ? Wl0mc[k * 128 + n] : Wr0mc[(k - 64) * 128 + n];
        cvt_split(v, g_b0mc[0], g_b0mc[1], n * 128 + k);
    } else if (i < 65536) {
        int j = i - 32768; int k = j >> 7, n = j & 127;
        float v = (k < 128) ? Wl1cm[k * 128 + n] : Wr1cm[(k - 128) * 128 + n];
        cvt_split(v, g_b1cm[0], g_b1cm[1], n * 256 + k);
    } else if (i < 98304) {
        int j = i - 65536; int k = j >> 7, n = j & 127;
        float v = (k < 128) ? Wl1mc[k * 128 + n] : Wr1mc[(k - 128) * 128 + n];
        cvt_split(v, g_b1mc[0], g_b1mc[1], n * 256 + k);
    } else if (i < 114688) {
        int j = i - 98304; int k = j >> 7, n = j & 127;
        float v = (n < 64) ? cW1c[k * 64 + n] : rW1[k * 64 + (n - 64)];
        cvt_split(v, g_bhc[0], g_bhc[1], n * 128 + k);
    } else if (i < 131072) {
        int j = i - 114688; int k = j >> 7, n = j & 127;
        float v = (n < 64) ? cW1m[k * 64 + n] : rW1[k * 64 + (n - 64)];
        cvt_split(v, g_bhm[0], g_bhm[1], n * 128 + k);
    }
}

// ---------------- gather-style mean aggregation (unrolled x2 for MLP) ----------------
template <int GRAPH, int KVEC, int XS>
__global__ void k_aggregate(const float* __restrict__ xext) {
    const int* __restrict__ off = GRAPH ? g_off_c : g_off_m;
    const int* __restrict__ cnt = GRAPH ? g_cnt_c : g_cnt_m;
    const int* __restrict__ csr = GRAPH ? g_csr_mc : g_csr_cm;
    float* __restrict__ mean = GRAPH ? g_mean_c : g_mean_m;
    const int nn = GRAPH ? NC : NM;
    const float* __restrict__ xsrc = (XS == 0) ? xext : (XS == 1 ? g_hm : g_hc);

    int w = (blockIdx.x * blockDim.x + threadIdx.x) >> 5;
    if (w >= nn) return;
    int lane = threadIdx.x & 31;
    int n = cnt[w];
    int b = off[w], e = b + n;
    float r = 1.f / fmaxf((float)n, 1.f);

    if (KVEC == 2) {
        float ax = 0.f, ay = 0.f, bx = 0.f, by = 0.f;
        int j = b;
        for (; j + 2 <= e; j += 2) {
            int s0 = csr[j], s1 = csr[j + 1];
            float2 v0 = ((const float2*)(xsrc + (size_t)s0 * 64))[lane];
            float2 v1 = ((const float2*)(xsrc + (size_t)s1 * 64))[lane];
            ax += v0.x; ay += v0.y;
            bx += v1.x; by += v1.y;
        }
        if (j < e) {
            int s0 = csr[j];
            float2 v0 = ((const float2*)(xsrc + (size_t)s0 * 64))[lane];
            ax += v0.x; ay += v0.y;
        }
        ((float2*)(mean + (size_t)w * 64))[lane] = make_float2((ax + bx) * r, (ay + by) * r);
    } else {
        float ax = 0.f, ay = 0.f, az = 0.f, aw = 0.f;
        float bx = 0.f, by = 0.f, bz = 0.f, bw = 0.f;
        int j = b;
        for (; j + 2 <= e; j += 2) {
            int s0 = csr[j], s1 = csr[j + 1];
            float4 v0 = ((const float4*)(xsrc + (size_t)s0 * 128))[lane];
            float4 v1 = ((const float4*)(xsrc + (size_t)s1 * 128))[lane];
            ax += v0.x; ay += v0.y; az += v0.z; aw += v0.w;
            bx += v1.x; by += v1.y; bz += v1.z; bw += v1.w;
        }
        if (j < e) {
            int s0 = csr[j];
            float4 v0 = ((const float4*)(xsrc + (size_t)s0 * 128))[lane];
            ax += v0.x; ay += v0.y; az += v0.z; aw += v0.w;
        }
        float4 o;
        o.x = (ax + bx) * r; o.y = (ay + by) * r;
        o.z = (az + bz) * r; o.w = (aw + bw) * r;
        ((float4*)(mean + (size_t)w * 128))[lane] = o;
    }
}

// ---------------- bf16-split tensor-core GEMM (mma.sync, software-pipelined) ----------------
// C[128 x 128] per block; 8 warps as 4(row) x 2(col); warp tile 32x64.
// Register-prefetch of next chunk's A (fp32) and B (bf16) overlaps LDG with MMA.
template <int EPI, int ASEL, int XSEL, int OSEL, int WSEL>
__global__ __launch_bounds__(256) void k_mma(
    const float* __restrict__ xext, float* __restrict__ oext,
    const float* __restrict__ bias, const float* __restrict__ hb2,
    const float* __restrict__ cW2, const float* __restrict__ cb2,
    const float* __restrict__ rW2, const float* __restrict__ rb2,
    float* __restrict__ pred, float* __restrict__ risk,
    int nrows, int KH, int KTOT) {
    __shared__ __align__(16) __nv_bfloat16 Ah[128][40], Al[128][40], Bh[128][40], Bl[128][40];
    __shared__ float b1s[128];
    __shared__ float cw2s[128];
    __shared__ float rw2s[64];
    __shared__ float cb2s[2], rb2s[1];

    const __nv_bfloat16* bt_hi =
        (WSEL == 0) ? g_b0cm[0] : (WSEL == 1) ? g_b0mc[0] : (WSEL == 2) ? g_b1cm[0]
        : (WSEL == 3) ? g_b1mc[0] : (WSEL == 4) ? g_bhc[0] : g_bhm[0];
    const __nv_bfloat16* bt_lo =
        (WSEL == 0) ? g_b0cm[1] : (WSEL == 1) ? g_b0mc[1] : (WSEL == 2) ? g_b1cm[1]
        : (WSEL == 3) ? g_b1mc[1] : (WSEL == 4) ? g_bhc[1] : g_bhm[1];

    const float* a0 = (ASEL == 0) ? g_mean_m : (ASEL == 1 ? g_mean_c : xext);
    const float* a1 = (XSEL == 0) ? xext : (XSEL == 1 ? g_hm : g_hc);
    float* out = (OSEL == 0) ? oext : (OSEL == 1 ? g_hm : g_hc);

    int t = threadIdx.x;
    int wid = t >> 5, lane = t & 31;
    int wr = wid >> 1, wc = wid & 1;
    int row0 = blockIdx.x * 128;

    if (EPI == 0) {
        if (t < 128) b1s[t] = bias[t];
    } else {
        if (t < 64) { b1s[t] = bias[t]; b1s[64 + t] = hb2[t]; rw2s[t] = rW2[t]; }
        if (t >= 128 && t < 256) cw2s[t - 128] = cW2[t - 128];
        if (t == 64) { cb2s[0] = cb2[0]; cb2s[1] = cb2[1]; rb2s[0] = rb2[0]; }
    }

    float acc[2][8][4];
#pragma unroll
    for (int m = 0; m < 2; m++)
#pragma unroll
        for (int n = 0; n < 8; n++)
#pragma unroll
            for (int j = 0; j < 4; j++) acc[m][n][j] = 0.f;

    int lrow = t >> 1;
    int kq = (t & 1) * 16;
    int grow = row0 + lrow;
    if (grow >= nrows) grow = nrows - 1;

    int nch = KTOT >> 5;

    // prefetch registers
    float4 av[4];
    uint4 bvh[2], bvl[2];
    {
        const float* srcp = (0 < KH) ? a0 + (size_t)grow * KH + kq
                                     : a1 + (size_t)grow * KH + (0 - KH) + kq;
#pragma unroll
        for (int j = 0; j < 4; j++) av[j] = *(const float4*)(srcp + j * 4);
        const __nv_bfloat16* sh = bt_hi + (size_t)lrow * KTOT + kq;
        const __nv_bfloat16* sl = bt_lo + (size_t)lrow * KTOT + kq;
        bvh[0] = ((const uint4*)sh)[0]; bvh[1] = ((const uint4*)sh)[1];
        bvl[0] = ((const uint4*)sl)[0]; bvl[1] = ((const uint4*)sl)[1];
    }

    for (int ch = 0; ch < nch; ch++) {
        // ---- store prefetched regs into smem (split A to hi/lo) ----
#pragma unroll
        for (int j = 0; j < 4; j++) {
            float4 v = av[j];
            __nv_bfloat162 h01 = __float22bfloat162_rn(make_float2(v.x, v.y));
            __nv_bfloat162 h23 = __float22bfloat162_rn(make_float2(v.z, v.w));
            __nv_bfloat162 l01 = __float22bfloat162_rn(make_float2(
                v.x - __bfloat162float(h01.x), v.y - __bfloat162float(h01.y)));
            __nv_bfloat162 l23 = __float22bfloat162_rn(make_float2(
                v.z - __bfloat162float(h23.x), v.w - __bfloat162float(h23.y)));
            uint2 uh = make_uint2(*reinterpret_cast<unsigned*>(&h01),
                                  *reinterpret_cast<unsigned*>(&h23));
            uint2 ul = make_uint2(*reinterpret_cast<unsigned*>(&l01),
                                  *reinterpret_cast<unsigned*>(&l23));
            *(uint2*)&Ah[lrow][kq + j * 4] = uh;
            *(uint2*)&Al[lrow][kq + j * 4] = ul;
        }
        *(uint4*)&Bh[lrow][kq] = bvh[0]; *(uint4*)&Bh[lrow][kq + 8] = bvh[1];
        *(uint4*)&Bl[lrow][kq] = bvl[0]; *(uint4*)&Bl[lrow][kq + 8] = bvl[1];
        __syncthreads();

        // ---- issue next chunk's LDGs (latency hidden behind MMA below) ----
        if (ch + 1 < nch) {
            int gk = (ch + 1) * 32;
            const float* srcp = (gk < KH) ? a0 + (size_t)grow * KH + gk + kq
                                          : a1 + (size_t)grow * KH + (gk - KH) + kq;
#pragma unroll
            for (int j = 0; j < 4; j++) av[j] = *(const float4*)(srcp + j * 4);
            const __nv_bfloat16* sh = bt_hi + (size_t)lrow * KTOT + gk + kq;
            const __nv_bfloat16* sl = bt_lo + (size_t)lrow * KTOT + gk + kq;
            bvh[0] = ((const uint4*)sh)[0]; bvh[1] = ((const uint4*)sh)[1];
            bvl[0] = ((const uint4*)sl)[0]; bvl[1] = ((const uint4*)sl)[1];
        }

        int lr = lane & 15, lk = (lane >> 4) * 8;
#pragma unroll
        for (int kt = 0; kt < 2; kt++) {
            uint32_t a_h[2][4], a_l[2][4];
#pragma unroll
            for (int mt = 0; mt < 2; mt++) {
                ldsm4(a_h[mt], smem_u32(&Ah[wr * 32 + mt * 16 + lr][kt * 16 + lk]));
                ldsm4(a_l[mt], smem_u32(&Al[wr * 32 + mt * 16 + lr][kt * 16 + lk]));
            }
#pragma unroll
            for (int nb = 0; nb < 4; nb++) {
                uint32_t bh[4], bl[4];
                ldsm4(bh, smem_u32(&Bh[wc * 64 + nb * 16 + lr][kt * 16 + lk]));
                ldsm4(bl, smem_u32(&Bl[wc * 64 + nb * 16 + lr][kt * 16 + lk]));
#pragma unroll
                for (int sn = 0; sn < 2; sn++) {
#pragma unroll
                    for (int mt = 0; mt < 2; mt++) {
                        float* c = acc[mt][nb * 2 + sn];
                        mma_bf16(c, a_h[mt], bh[sn], bh[sn + 2]);
                        mma_bf16(c, a_h[mt], bl[sn], bl[sn + 2]);
                        mma_bf16(c, a_l[mt], bh[sn], bh[sn + 2]);
                    }
                }
            }
        }
        __syncthreads();
    }

    int q = lane & 3, rq = lane >> 2;
    if (EPI == 0) {
#pragma unroll
        for (int mt = 0; mt < 2; mt++) {
#pragma unroll
            for (int nf = 0; nf < 8; nf++) {
                int gc = wc * 64 + (nf >> 1) * 16 + (nf & 1) * 8 + q * 2;
                float b0 = b1s[gc], b1 = b1s[gc + 1];
                int r1 = row0 + wr * 32 + mt * 16 + rq;
                int r2 = r1 + 8;
                if (r1 < nrows) {
                    float2 v = make_float2(fmaxf(acc[mt][nf][0] + b0, 0.f),
                                           fmaxf(acc[mt][nf][1] + b1, 0.f));
                    *(float2*)&out[(size_t)r1 * 128 + gc] = v;
                }
                if (r2 < nrows) {
                    float2 v = make_float2(fmaxf(acc[mt][nf][2] + b0, 0.f),
                                           fmaxf(acc[mt][nf][3] + b1, 0.f));
                    *(float2*)&out[(size_t)r2 * 128 + gc] = v;
                }
            }
        }
    } else {
        // heads: wc=0 -> class (cols 0..63), wc=1 -> risk (cols 64..127)
#pragma unroll
        for (int mt = 0; mt < 2; mt++) {
#pragma unroll
            for (int h = 0; h < 2; h++) {
                int grow2 = row0 + wr * 32 + mt * 16 + h * 8 + rq;
                float p0 = 0.f, p1 = 0.f, rk = 0.f;
#pragma unroll
                for (int nf = 0; nf < 8; nf++) {
                    int gc = wc * 64 + (nf >> 1) * 16 + (nf & 1) * 8 + q * 2;
                    float T0 = fmaxf(acc[mt][nf][h * 2 + 0] + b1s[gc], 0.f);
                    float T1 = fmaxf(acc[mt][nf][h * 2 + 1] + b1s[gc + 1], 0.f);
                    if (wc == 0) {
                        p0 += T0 * cw2s[gc * 2] + T1 * cw2s[(gc + 1) * 2];
                        p1 += T0 * cw2s[gc * 2 + 1] + T1 * cw2s[(gc + 1) * 2 + 1];
                    } else {
                        rk += T0 * rw2s[gc - 64] + T1 * rw2s[gc + 1 - 64];
                    }
                }
                if (wc == 0) {
                    p0 += __shfl_xor_sync(0xffffffffu, p0, 1);
                    p0 += __shfl_xor_sync(0xffffffffu, p0, 2);
                    p1 += __shfl_xor_sync(0xffffffffu, p1, 1);
                    p1 += __shfl_xor_sync(0xffffffffu, p1, 2);
                    if (q == 0 && grow2 < nrows) {
                        pred[(size_t)grow2 * 2 + 0] = p0 + cb2s[0];
                        pred[(size_t)grow2 * 2 + 1] = p1 + cb2s[1];
                    }
                } else {
                    rk += __shfl_xor_sync(0xffffffffu, rk, 1);
                    rk += __shfl_xor_sync(0xffffffffu, rk, 2);
                    if (q == 0 && grow2 < nrows) {
                        float x = rk + rb2s[0];
                        risk[grow2] = 1.f / (1.f + __expf(-x));
                    }
                }
            }
        }
    }
}

// ---------------- launcher (fork-join multi-stream; created once, outside capture) ----------------
extern "C" void kernel_launch(void* const* d_in, const int* in_sizes, int n_in,
                              void* d_out, int out_size) {
    const float* x_card  = (const float*)d_in[0];
    const float* x_merch = (const float*)d_in[1];
    const int* src_cm = (const int*)d_in[2];
    const int* dst_cm = (const int*)d_in[3];
    const int* src_mc = (const int*)d_in[4];
    const int* dst_mc = (const int*)d_in[5];
    const float* Wl0_cm = (const float*)d_in[6];
    const float* bl0_cm = (const float*)d_in[7];
    const float* Wr0_cm = (const float*)d_in[8];
    const float* Wl0_mc = (const float*)d_in[9];
    const float* bl0_mc = (const float*)d_in[10];
    const float* Wr0_mc = (const float*)d_in[11];
    const float* Wl1_cm = (const float*)d_in[12];
    const float* bl1_cm = (const float*)d_in[13];
    const float* Wr1_cm = (const float*)d_in[14];
    const float* Wl1_mc = (const float*)d_in[15];
    const float* bl1_mc = (const float*)d_in[16];
    const float* Wr1_mc = (const float*)d_in[17];
    const float* cW1c = (const float*)d_in[18];
    const float* cb1c = (const float*)d_in[19];
    const float* cW2c = (const float*)d_in[20];
    const float* cb2c = (const float*)d_in[21];
    const float* cW1m = (const float*)d_in[22];
    const float* cb1m = (const float*)d_in[23];
    const float* cW2m = (const float*)d_in[24];
    const float* cb2m = (const float*)d_in[25];
    const float* rW1 = (const float*)d_in[26];
    const float* rb1 = (const float*)d_in[27];
    const float* rW2 = (const float*)d_in[28];
    const float* rb2 = (const float*)d_in[29];

    float* out = (float*)d_out;
    float* o_hc2 = out;
    float* o_hm2 = out + 12800000;
    float* o_pc  = out + 19200000;
    float* o_pm  = out + 19400000;
    float* o_rc  = out + 19500000;
    float* o_rm  = out + 19600000;

    // one-time stream/event creation (first call is the non-captured correctness run;
    // creation is host-side only — no device memory involved)
    static cudaStream_t s1 = nullptr, s2 = nullptr;
    static cudaEvent_t evF, evPrep, evFill, ev_hm, ev_hc, evEnd;
    if (s1 == nullptr) {
        cudaStreamCreateWithFlags(&s1, cudaStreamNonBlocking);
        cudaStreamCreateWithFlags(&s2, cudaStreamNonBlocking);
        cudaEventCreateWithFlags(&evF,    cudaEventDisableTiming);
        cudaEventCreateWithFlags(&evPrep, cudaEventDisableTiming);
        cudaEventCreateWithFlags(&evFill, cudaEventDisableTiming);
        cudaEventCreateWithFlags(&ev_hm,  cudaEventDisableTiming);
        cudaEventCreateWithFlags(&ev_hc,  cudaEventDisableTiming);
        cudaEventCreateWithFlags(&evEnd,  cudaEventDisableTiming);
    }

    // fork: weight prep runs on s1 concurrently with the CSR chain on stream 0
    cudaEventRecord(evF, 0);
    cudaStreamWaitEvent(s1, evF, 0);
    k_prep<<<512, 256, 0, s1>>>(Wl0_cm, Wr0_cm, Wl0_mc, Wr0_mc, Wl1_cm, Wr1_cm,
                                Wl1_mc, Wr1_mc, cW1c, cW1m, rW1);
    cudaEventRecord(evPrep, s1);

    // CSR build on stream 0
    k_zero<<<(NC + 255) / 256, 256>>>();
    k_count<<<1024, 256>>>(dst_cm, dst_mc);
    k_alloc<0><<<(NM + 255) / 256, 256>>>();
    k_alloc<1><<<(NC + 255) / 256, 256>>>();
    k_fill<<<1024, 256>>>(src_cm, dst_cm, src_mc, dst_mc);
    cudaEventRecord(evFill, 0);

    // fork card path onto s2
    cudaStreamWaitEvent(s2, evFill, 0);

    // ---- merchant path (stream 0) / card path (s2), layer 0 ----
    k_aggregate<0, 2, 0><<<(NM * 32 + 255) / 256, 256>>>(x_card);            // mean_m
    k_aggregate<1, 2, 0><<<(NC * 32 + 255) / 256, 256, 0, s2>>>(x_merch);    // mean_c

    cudaStreamWaitEvent(0, evPrep, 0);
    cudaStreamWaitEvent(s2, evPrep, 0);

    k_mma<0, 0, 0, 1, 0><<<(NM + 127) / 128, 256>>>(                         // h_m
        x_merch, nullptr, bl0_cm,
        nullptr, nullptr, nullptr, nullptr, nullptr, nullptr, nullptr, NM, 64, 128);
    cudaEventRecord(ev_hm, 0);
    k_mma<0, 1, 0, 2, 1><<<(NC + 127) / 128, 256, 0, s2>>>(                  // h_c
        x_card, nullptr, bl0_mc,
        nullptr, nullptr, nullptr, nullptr, nullptr, nullptr, nullptr, NC, 64, 128);
    cudaEventRecord(ev_hc, s2);

    // ---- layer 1 (cross dependencies: agg gathers the other type's h) ----
    cudaStreamWaitEvent(0, ev_hc, 0);   // agg1_m gathers h_c
    k_aggregate<0, 4, 2><<<(NM * 32 + 255) / 256, 256>>>(nullptr);           // mean_m <- h_c
    cudaStreamWaitEvent(s2, ev_hm, 0);  // agg1_c gathers h_m
    k_aggregate<1, 4, 1><<<(NC * 32 + 255) / 256, 256, 0, s2>>>(nullptr);    // mean_c <- h_m

    k_mma<0, 0, 1, 0, 2><<<(NM + 127) / 128, 256>>>(                         // h_m2
        nullptr, o_hm2, bl1_cm,
        nullptr, nullptr, nullptr, nullptr, nullptr, nullptr, nullptr, NM, 128, 256);
    k_mma<0, 1, 2, 0, 3><<<(NC + 127) / 128, 256, 0, s2>>>(                  // h_c2
        nullptr, o_hc2, bl1_mc,
        nullptr, nullptr, nullptr, nullptr, nullptr, nullptr, nullptr, NC, 128, 256);

    // ---- heads ----
    k_mma<1, 2, 0, 0, 5><<<(NM + 127) / 128, 256>>>(
        o_hm2, nullptr, cb1m,
        rb1, cW2m, cb2m, rW2, rb2, o_pm, o_rm, NM, 128, 128);
    k_mma<1, 2, 0, 0, 4><<<(NC + 127) / 128, 256, 0, s2>>>(
        o_hc2, nullptr, cb1c,
        rb1, cW2c, cb2c, rW2, rb2, o_pc, o_rc, NC, 128, 128);

    // join card path back into stream 0
    cudaEventRecord(evEnd, s2);
    cudaStreamWaitEvent(0, evEnd, 0);
}